// round 1
// baseline (speedup 1.0000x reference)
#include <cuda_runtime.h>
#include <math.h>

#define BATCH 4
#define SEQ   4096
#define DIM   1024
#define MROWS (BATCH*SEQ)       // 16384
#define NCH   128               // chunks per batch for bind-accumulate
#define CROWS (SEQ / NCH)       // 32 rows per chunk

// -------- scratch (static device globals; no runtime allocation) -----------
__device__ float  g_q[MROWS*DIM];
__device__ float  g_k[MROWS*DIM];
__device__ float  g_v[MROWS*DIM];
__device__ float  g_r[MROWS*DIM];
__device__ float2 g_part[BATCH*NCH*DIM];
__device__ float2 g_Fs[BATCH*DIM];

// -------- complex helpers ---------------------------------------------------
__device__ __forceinline__ float2 cmulf(float2 a, float2 b) {
    return make_float2(fmaf(a.x, b.x, -a.y * b.y), fmaf(a.x, b.y, a.y * b.x));
}

// ============================================================================
// GEMM: C[i,e] = tanh( sum_d A[i,d] * W[e,d] + bias[e] )   (both K-contiguous)
// BM=BN=128, BK=8, 256 threads, 8x8 per thread.
// ============================================================================
#define BM 128
#define BN 128
#define BKK 8

__global__ void __launch_bounds__(256, 2) gemm_tanh_kernel(
    const float* __restrict__ A, const float* __restrict__ W,
    const float* __restrict__ bias, int sel)
{
    float* C = (sel == 0) ? g_q : (sel == 1) ? g_k : (sel == 2) ? g_v : g_r;

    __shared__ float sA[BKK][BM];
    __shared__ float sB[BKK][BN];

    const int bm = blockIdx.y * BM;
    const int bn = blockIdx.x * BN;
    const int tid = threadIdx.x;
    const int lr = tid >> 1;            // 0..127
    const int lc = (tid & 1) << 2;      // 0 or 4
    const int tx = tid & 15;
    const int ty = tid >> 4;

    const float* Ap = A + (size_t)(bm + lr) * DIM + lc;
    const float* Wp = W + (size_t)(bn + lr) * DIM + lc;

    float acc[8][8];
#pragma unroll
    for (int i = 0; i < 8; i++)
#pragma unroll
        for (int j = 0; j < 8; j++) acc[i][j] = 0.f;

    for (int k0 = 0; k0 < DIM; k0 += BKK) {
        float4 a4 = *(const float4*)(Ap + k0);
        float4 b4 = *(const float4*)(Wp + k0);
        __syncthreads();
        sA[lc + 0][lr] = a4.x; sA[lc + 1][lr] = a4.y;
        sA[lc + 2][lr] = a4.z; sA[lc + 3][lr] = a4.w;
        sB[lc + 0][lr] = b4.x; sB[lc + 1][lr] = b4.y;
        sB[lc + 2][lr] = b4.z; sB[lc + 3][lr] = b4.w;
        __syncthreads();
#pragma unroll
        for (int kk = 0; kk < BKK; kk++) {
            float ra[8], rb[8];
#pragma unroll
            for (int i = 0; i < 8; i++) ra[i] = sA[kk][ty * 8 + i];
#pragma unroll
            for (int j = 0; j < 8; j++) rb[j] = sB[kk][tx * 8 + j];
#pragma unroll
            for (int i = 0; i < 8; i++)
#pragma unroll
                for (int j = 0; j < 8; j++)
                    acc[i][j] = fmaf(ra[i], rb[j], acc[i][j]);
        }
    }

#pragma unroll
    for (int i = 0; i < 8; i++) {
        const int row = bm + ty * 8 + i;
        float* cp = C + (size_t)row * DIM + bn + tx * 8;
#pragma unroll
        for (int j = 0; j < 8; j++)
            cp[j] = tanhf(acc[i][j] + bias[bn + tx * 8 + j]);
    }
}

// ============================================================================
// In-block Stockham FFT, N=1024, 256 threads, ping-pong shared buffers.
// Twiddle table tw[m] = exp(-i*pi*m/512). inv=1 conjugates (no 1/N scaling).
// Result ends in the buffer passed as 'a'.
// ============================================================================
__device__ float2* fft1024(float2* a, float2* b, const float2* tw, int t, int inv)
{
    int m = 1;
#pragma unroll
    for (int s = 0; s < 10; s++) {
        __syncthreads();
#pragma unroll
        for (int h = 0; h < 2; h++) {
            const int u  = t + (h << 8);
            const int k  = u & (m - 1);
            const int jm = u - k;               // j*m
            float2 x0 = a[u];
            float2 x1 = a[u + 512];
            float2 w  = tw[jm];
            if (inv) w.y = -w.y;
            float2 sum = make_float2(x0.x + x1.x, x0.y + x1.y);
            float2 dif = make_float2(x0.x - x1.x, x0.y - x1.y);
            b[2 * jm + k]     = sum;
            b[2 * jm + k + m] = cmulf(w, dif);
        }
        float2* tmp = a; a = b; b = tmp;
        m <<= 1;
    }
    __syncthreads();
    return a;
}

__device__ __forceinline__ void build_tw(float2* tw, int t)
{
    for (int i = t; i < 512; i += 256) {
        float sn, cs;
        sincosf(-(float)M_PI * (float)i * (1.0f / 512.0f), &sn, &cs);
        tw[i] = make_float2(cs, sn);
    }
}

// ============================================================================
// Kernel 2: per chunk of 32 rows: Z = FFT(k + i*v); extract Fk, Fv by Hermitian
// symmetry; accumulate Fk*Fv into per-chunk partial sums.
// ============================================================================
__global__ void __launch_bounds__(256) bind_accum_kernel()
{
    __shared__ float2 tw[512];
    __shared__ float2 bufA[1024];
    __shared__ float2 bufB[1024];

    const int t = threadIdx.x;
    const int c = blockIdx.x;
    const int b = blockIdx.y;
    build_tw(tw, t);

    float2 acc[4];
#pragma unroll
    for (int h = 0; h < 4; h++) acc[h] = make_float2(0.f, 0.f);

    const size_t base = ((size_t)b * SEQ + (size_t)c * CROWS) * DIM;
    for (int r = 0; r < CROWS; r++) {
        const float* kp = g_k + base + (size_t)r * DIM;
        const float* vp = g_v + base + (size_t)r * DIM;
#pragma unroll
        for (int h = 0; h < 4; h++) {
            const int i = t + (h << 8);
            bufA[i] = make_float2(kp[i], vp[i]);
        }
        float2* Z = fft1024(bufA, bufB, tw, t, 0);
#pragma unroll
        for (int h = 0; h < 4; h++) {
            const int f  = t + (h << 8);
            const int fn = (1024 - f) & 1023;
            const float2 z1 = Z[f];
            const float2 z2 = Z[fn];
            // Fk = 0.5*(Z[f] + conj(Z[-f]));  Fv = (Z[f] - conj(Z[-f]))/(2i)
            const float2 Fk = make_float2(0.5f * (z1.x + z2.x), 0.5f * (z1.y - z2.y));
            const float dx = z1.x - z2.x, dy = z1.y + z2.y;
            const float2 Fv = make_float2(0.5f * dy, -0.5f * dx);
            const float2 p = cmulf(Fk, Fv);
            acc[h].x += p.x; acc[h].y += p.y;
        }
        __syncthreads();  // all Z reads done before next row overwrites bufA
    }

    float2* outp = g_part + ((size_t)b * NCH + c) * DIM;
#pragma unroll
    for (int h = 0; h < 4; h++) outp[t + (h << 8)] = acc[h];
}

// Fixed-order reduction of chunk partials -> Fs (deterministic)
__global__ void reduce_Fs_kernel()
{
    const int f = blockIdx.x * 256 + threadIdx.x;   // grid.x = DIM/256
    const int b = blockIdx.y;
    float2 s = make_float2(0.f, 0.f);
    const float2* p = g_part + (size_t)b * NCH * DIM + f;
    for (int c = 0; c < NCH; c++) {
        const float2 v = p[(size_t)c * DIM];
        s.x += v.x; s.y += v.y;
    }
    g_Fs[b * DIM + f] = s;
}

// ============================================================================
// Kernel 3: per row: Z = FFT(q + i*r); G = conj(Fq) - |Fr|^2;
// out = x + ifft(G * Fs[b]).real
// ============================================================================
__global__ void __launch_bounds__(256) output_kernel(
    const float* __restrict__ x, float* __restrict__ out)
{
    __shared__ float2 tw[512];
    __shared__ float2 bufA[1024];
    __shared__ float2 bufB[1024];

    const int t = threadIdx.x;
    const int row = blockIdx.x;
    const int b = row >> 12;                 // 4096 rows per batch
    build_tw(tw, t);

    const size_t base = (size_t)row * DIM;
    const float* qp = g_q + base;
    const float* rp = g_r + base;
#pragma unroll
    for (int h = 0; h < 4; h++) {
        const int i = t + (h << 8);
        bufA[i] = make_float2(qp[i], rp[i]);
    }
    float2* Z = fft1024(bufA, bufB, tw, t, 0);   // Z == bufA

    const float2* Fsb = g_Fs + (size_t)b * DIM;
#pragma unroll
    for (int h = 0; h < 4; h++) {
        const int f  = t + (h << 8);
        const int fn = (1024 - f) & 1023;
        const float2 z1 = Z[f];
        const float2 z2 = Z[fn];
        const float2 Fq = make_float2(0.5f * (z1.x + z2.x), 0.5f * (z1.y - z2.y));
        const float dx = z1.x - z2.x, dy = z1.y + z2.y;
        const float2 Fr = make_float2(0.5f * dy, -0.5f * dx);
        const float mag2 = Fr.x * Fr.x + Fr.y * Fr.y;
        const float2 G = make_float2(Fq.x - mag2, -Fq.y);
        bufB[f] = cmulf(G, Fsb[f]);              // H into the other buffer
    }
    // ifft(H): initial sync inside fft1024 orders Z reads / H writes vs overwrite
    float2* res = fft1024(bufB, bufA, tw, t, 1); // res == bufB

    const float* xp = x + base;
    float* op = out + base;
#pragma unroll
    for (int h = 0; h < 4; h++) {
        const int i = t + (h << 8);
        op[i] = xp[i] + res[i].x * (1.0f / 1024.0f);
    }
}

// ============================================================================
// Launch
// ============================================================================
extern "C" void kernel_launch(void* const* d_in, const int* in_sizes, int n_in,
                              void* d_out, int out_size)
{
    const float* x  = (const float*)d_in[0];
    const float* Wq = (const float*)d_in[1];
    const float* bq = (const float*)d_in[2];
    const float* Wk = (const float*)d_in[3];
    const float* bk = (const float*)d_in[4];
    const float* Wv = (const float*)d_in[5];
    const float* bv = (const float*)d_in[6];
    const float* Wr = (const float*)d_in[7];
    const float* br = (const float*)d_in[8];
    float* out = (float*)d_out;

    dim3 gg(DIM / BN, MROWS / BM);   // (8, 128)
    gemm_tanh_kernel<<<gg, 256>>>(x, Wq, bq, 0);
    gemm_tanh_kernel<<<gg, 256>>>(x, Wk, bk, 1);
    gemm_tanh_kernel<<<gg, 256>>>(x, Wv, bv, 2);
    gemm_tanh_kernel<<<gg, 256>>>(x, Wr, br, 3);

    bind_accum_kernel<<<dim3(NCH, BATCH), 256>>>();
    reduce_Fs_kernel<<<dim3(DIM / 256, BATCH), 256>>>();
    output_kernel<<<MROWS, 256>>>(x, out);
}

// round 3
// speedup vs baseline: 2.7051x; 2.7051x over previous
#include <cuda_runtime.h>
#include <cuda_bf16.h>
#include <math.h>
#include <stdint.h>

#define BATCH 4
#define SEQ   4096
#define DIM   1024
#define MROWS (BATCH*SEQ)       // 16384
#define KSTORE 2048             // [hi | lo] per row, bf16
#define NCH   128
#define CROWS (SEQ / NCH)

// ---- mma.sync GEMM tiling ----
#define BM 128
#define BN 128
#define BKE 64                  // bf16 K-elems per stage (128 bytes/row)
#define KITERS 48               // 3072 effective K (3-term split)
#define STAGES 3
#define A_ST (BM * 128)         // 16384 B
#define B_ST (BN * 128)         // 16384 B
#define STAGE_B (A_ST + B_ST)   // 32768
#define SMEM_DYN (STAGES * STAGE_B)   // 98304

// -------- scratch (static device globals; no runtime allocation) -----------
__device__ __nv_bfloat16 g_xe[(size_t)MROWS * KSTORE];   // 64MB  [row][ah(1024)|al(1024)]
__device__ __nv_bfloat16 g_we[4][(size_t)DIM * KSTORE];  // 16MB  [w][row][bh|bl]
__device__ float  g_q[(size_t)MROWS * DIM];
__device__ float  g_k[(size_t)MROWS * DIM];
__device__ float  g_v[(size_t)MROWS * DIM];
__device__ float  g_r[(size_t)MROWS * DIM];
__device__ float2 g_part[BATCH * NCH * DIM];
__device__ float2 g_Fs[BATCH * DIM];

// ============================================================================
// helpers
// ============================================================================
__device__ __forceinline__ uint32_t smem_u32(const void* p) {
    uint32_t a;
    asm("{ .reg .u64 t; cvta.to.shared.u64 t, %1; cvt.u32.u64 %0, t; }" : "=r"(a) : "l"(p));
    return a;
}

__device__ __forceinline__ void cp16(uint32_t dst, const void* src) {
    asm volatile("cp.async.cg.shared.global [%0], [%1], 16;" :: "r"(dst), "l"(src) : "memory");
}
#define CP_COMMIT() asm volatile("cp.async.commit_group;" ::: "memory")
#define CP_WAIT1()  asm volatile("cp.async.wait_group 1;" ::: "memory")

__device__ __forceinline__ void ldmx4(uint32_t& r0, uint32_t& r1, uint32_t& r2, uint32_t& r3,
                                      uint32_t addr) {
    asm volatile("ldmatrix.sync.aligned.m8n8.x4.shared.b16 {%0,%1,%2,%3}, [%4];"
                 : "=r"(r0), "=r"(r1), "=r"(r2), "=r"(r3) : "r"(addr));
}

__device__ __forceinline__ void mma16816(float* c, uint32_t a0, uint32_t a1, uint32_t a2,
                                         uint32_t a3, uint32_t b0, uint32_t b1) {
    asm volatile(
        "mma.sync.aligned.m16n8k16.row.col.f32.bf16.bf16.f32 "
        "{%0,%1,%2,%3}, {%4,%5,%6,%7}, {%8,%9}, {%0,%1,%2,%3};"
        : "+f"(c[0]), "+f"(c[1]), "+f"(c[2]), "+f"(c[3])
        : "r"(a0), "r"(a1), "r"(a2), "r"(a3), "r"(b0), "r"(b1));
}

__device__ __forceinline__ float tanh_fast(float x) {
    float ax = fabsf(x);
    float e = __expf(-2.0f * ax);
    float t = __fdividef(1.0f - e, 1.0f + e);
    return copysignf(t, x);
}

// swizzled smem byte offset within a 128-row x 128-byte tile
__device__ __forceinline__ uint32_t swz(uint32_t row, uint32_t cg) {
    return row * 128u + ((cg ^ (row & 7u)) << 4);
}

// ============================================================================
// Conversion: fp32 -> hi/lo bf16 halves  (row-major, [hi(1024) | lo(1024)])
// ============================================================================
__global__ void __launch_bounds__(256) convert_x_kernel(const float* __restrict__ x)
{
    const size_t idx = (size_t)blockIdx.x * 256 + threadIdx.x;   // 16.7M threads
    const size_t row = idx >> 10, d = idx & 1023;
    float v = x[idx];
    __nv_bfloat16 hi = __float2bfloat16(v);
    __nv_bfloat16 lo = __float2bfloat16(v - __bfloat162float(hi));
    g_xe[row * KSTORE + d]        = hi;
    g_xe[row * KSTORE + 1024 + d] = lo;
}

__global__ void __launch_bounds__(256) convert_w_kernel(
    const float* __restrict__ Wq, const float* __restrict__ Wk,
    const float* __restrict__ Wv, const float* __restrict__ Wr)
{
    const int w = blockIdx.y;
    const float* W = (w == 0) ? Wq : (w == 1) ? Wk : (w == 2) ? Wv : Wr;
    const size_t idx = (size_t)blockIdx.x * 256 + threadIdx.x;   // 1M threads
    const size_t row = idx >> 10, d = idx & 1023;
    float v = W[idx];
    __nv_bfloat16 hi = __float2bfloat16(v);
    __nv_bfloat16 lo = __float2bfloat16(v - __bfloat162float(hi));
    g_we[w][row * KSTORE + d]        = hi;
    g_we[w][row * KSTORE + 1024 + d] = lo;
}

// ============================================================================
// bf16 mma.sync GEMM with 3-term split:
//   C = tanh( Ah@Bh^T + Al@Bh^T + Ah@Bl^T + bias )
// K-iter kc in [0,48): a_chunk = kc<32 ? kc : kc-32 ; b_chunk = kc<16 ? kc : kc-16
// ============================================================================
__global__ void __launch_bounds__(256, 1) gemm_mma_kernel(
    const float* __restrict__ bq, const float* __restrict__ bk,
    const float* __restrict__ bv, const float* __restrict__ br)
{
    extern __shared__ char dsm[];
    const uint32_t smem = smem_u32(dsm);

    const int tid = threadIdx.x, wid = tid >> 5, lane = tid & 31;
    const int nb = blockIdx.x, mb = blockIdx.y, sel = blockIdx.z;
    const int wm = wid & 1, wn = wid >> 1;       // warp tile 64(m) x 32(n)
    const float* bias = (sel == 0) ? bq : (sel == 1) ? bk : (sel == 2) ? bv : br;
    float* C = (sel == 0) ? g_q : (sel == 1) ? g_k : (sel == 2) ? g_v : g_r;

    const char* a_base = (const char*)g_xe + (size_t)mb * BM * (KSTORE * 2);
    const char* b_base = (const char*)g_we[sel] + (size_t)nb * BN * (KSTORE * 2);

    // per-thread copy coords: 4 chunks of 16B per operand per stage
    const uint32_t crow[4] = { (uint32_t)(tid >> 3), (uint32_t)((tid + 256) >> 3),
                               (uint32_t)((tid + 512) >> 3), (uint32_t)((tid + 768) >> 3) };
    const uint32_t ccg = (uint32_t)(tid & 7);

    float acc[4][4][4];
#pragma unroll
    for (int i = 0; i < 4; i++)
#pragma unroll
        for (int j = 0; j < 4; j++)
#pragma unroll
            for (int q = 0; q < 4; q++) acc[i][j][q] = 0.f;

    auto issue = [&](int stage, int kc) {
        const int akc = (kc < 32) ? kc : kc - 32;
        const int bkc = (kc < 16) ? kc : kc - 16;
        const uint32_t sA = smem + stage * STAGE_B;
        const uint32_t sB = sA + A_ST;
#pragma unroll
        for (int j = 0; j < 4; j++) {
            const uint32_t r = crow[j];
            cp16(sA + swz(r, ccg), a_base + (size_t)r * 4096 + akc * 128 + ccg * 16);
            cp16(sB + swz(r, ccg), b_base + (size_t)r * 4096 + bkc * 128 + ccg * 16);
        }
    };

    issue(0, 0); CP_COMMIT();
    issue(1, 1); CP_COMMIT();

    // ldmatrix lane coords
    const uint32_t a_row = (uint32_t)(wm * 64 + (lane & 15));    // + mf*16
    const uint32_t a_kg  = (uint32_t)(lane >> 4);                // + ks*2
    const uint32_t b_row = (uint32_t)(wn * 32 + (lane & 7) + ((lane >> 4) << 3)); // + nf2*16
    const uint32_t b_kg  = (uint32_t)((lane >> 3) & 1);          // + ks*2

    for (int kc = 0; kc < KITERS; kc++) {
        const int s = kc % STAGES;
        CP_WAIT1();
        __syncthreads();
        const uint32_t sA = smem + s * STAGE_B;
        const uint32_t sB = sA + A_ST;
#pragma unroll
        for (int ks = 0; ks < 4; ks++) {
            uint32_t a[4][4];
#pragma unroll
            for (int mf = 0; mf < 4; mf++)
                ldmx4(a[mf][0], a[mf][1], a[mf][2], a[mf][3],
                      sA + swz(a_row + mf * 16, a_kg + ks * 2));
            uint32_t b[2][4];
#pragma unroll
            for (int nf2 = 0; nf2 < 2; nf2++)
                ldmx4(b[nf2][0], b[nf2][1], b[nf2][2], b[nf2][3],
                      sB + swz(b_row + nf2 * 16, b_kg + ks * 2));
#pragma unroll
            for (int mf = 0; mf < 4; mf++) {
#pragma unroll
                for (int nf2 = 0; nf2 < 2; nf2++) {
                    mma16816(acc[mf][nf2 * 2 + 0], a[mf][0], a[mf][1], a[mf][2], a[mf][3],
                             b[nf2][0], b[nf2][1]);
                    mma16816(acc[mf][nf2 * 2 + 1], a[mf][0], a[mf][1], a[mf][2], a[mf][3],
                             b[nf2][2], b[nf2][3]);
                }
            }
        }
        if (kc + 2 < KITERS) issue((kc + 2) % STAGES, kc + 2);
        CP_COMMIT();
    }

    // epilogue: bias + tanh + fp32 store
#pragma unroll
    for (int mf = 0; mf < 4; mf++) {
        const int r0 = mb * BM + wm * 64 + mf * 16 + (lane >> 2);
        const int r1 = r0 + 8;
#pragma unroll
        for (int nf = 0; nf < 4; nf++) {
            const int col = nb * BN + wn * 32 + nf * 8 + (lane & 3) * 2;
            const float2 b2 = *(const float2*)(bias + col);
            float2 o0, o1;
            o0.x = tanh_fast(acc[mf][nf][0] + b2.x);
            o0.y = tanh_fast(acc[mf][nf][1] + b2.y);
            o1.x = tanh_fast(acc[mf][nf][2] + b2.x);
            o1.y = tanh_fast(acc[mf][nf][3] + b2.y);
            *(float2*)(C + (size_t)r0 * DIM + col) = o0;
            *(float2*)(C + (size_t)r1 * DIM + col) = o1;
        }
    }
}

// ============================================================================
// FFT machinery (unchanged)
// ============================================================================
__device__ __forceinline__ float2 cmulf(float2 a, float2 b) {
    return make_float2(fmaf(a.x, b.x, -a.y * b.y), fmaf(a.x, b.y, a.y * b.x));
}

__device__ float2* fft1024(float2* a, float2* b, const float2* tw, int t, int inv)
{
    int m = 1;
#pragma unroll
    for (int s = 0; s < 10; s++) {
        __syncthreads();
#pragma unroll
        for (int h = 0; h < 2; h++) {
            const int u  = t + (h << 8);
            const int k  = u & (m - 1);
            const int jm = u - k;
            float2 x0 = a[u];
            float2 x1 = a[u + 512];
            float2 w  = tw[jm];
            if (inv) w.y = -w.y;
            float2 sum = make_float2(x0.x + x1.x, x0.y + x1.y);
            float2 dif = make_float2(x0.x - x1.x, x0.y - x1.y);
            b[2 * jm + k]     = sum;
            b[2 * jm + k + m] = cmulf(w, dif);
        }
        float2* tmp = a; a = b; b = tmp;
        m <<= 1;
    }
    __syncthreads();
    return a;
}

__device__ __forceinline__ void build_tw(float2* tw, int t)
{
    for (int i = t; i < 512; i += 256) {
        float sn, cs;
        sincosf(-(float)M_PI * (float)i * (1.0f / 512.0f), &sn, &cs);
        tw[i] = make_float2(cs, sn);
    }
}

__global__ void __launch_bounds__(256) bind_accum_kernel()
{
    __shared__ float2 tw[512];
    __shared__ float2 bufA[1024];
    __shared__ float2 bufB[1024];

    const int t = threadIdx.x;
    const int c = blockIdx.x;
    const int b = blockIdx.y;
    build_tw(tw, t);

    float2 acc[4];
#pragma unroll
    for (int h = 0; h < 4; h++) acc[h] = make_float2(0.f, 0.f);

    const size_t base = ((size_t)b * SEQ + (size_t)c * CROWS) * DIM;
    for (int r = 0; r < CROWS; r++) {
        const float* kp = g_k + base + (size_t)r * DIM;
        const float* vp = g_v + base + (size_t)r * DIM;
#pragma unroll
        for (int h = 0; h < 4; h++) {
            const int i = t + (h << 8);
            bufA[i] = make_float2(kp[i], vp[i]);
        }
        float2* Z = fft1024(bufA, bufB, tw, t, 0);
#pragma unroll
        for (int h = 0; h < 4; h++) {
            const int f  = t + (h << 8);
            const int fn = (1024 - f) & 1023;
            const float2 z1 = Z[f];
            const float2 z2 = Z[fn];
            const float2 Fk = make_float2(0.5f * (z1.x + z2.x), 0.5f * (z1.y - z2.y));
            const float dx = z1.x - z2.x, dy = z1.y + z2.y;
            const float2 Fv = make_float2(0.5f * dy, -0.5f * dx);
            const float2 p = cmulf(Fk, Fv);
            acc[h].x += p.x; acc[h].y += p.y;
        }
        __syncthreads();
    }

    float2* outp = g_part + ((size_t)b * NCH + c) * DIM;
#pragma unroll
    for (int h = 0; h < 4; h++) outp[t + (h << 8)] = acc[h];
}

__global__ void reduce_Fs_kernel()
{
    const int f = blockIdx.x * 256 + threadIdx.x;
    const int b = blockIdx.y;
    float2 s = make_float2(0.f, 0.f);
    const float2* p = g_part + (size_t)b * NCH * DIM + f;
    for (int c = 0; c < NCH; c++) {
        const float2 v = p[(size_t)c * DIM];
        s.x += v.x; s.y += v.y;
    }
    g_Fs[b * DIM + f] = s;
}

__global__ void __launch_bounds__(256) output_kernel(
    const float* __restrict__ x, float* __restrict__ out)
{
    __shared__ float2 tw[512];
    __shared__ float2 bufA[1024];
    __shared__ float2 bufB[1024];

    const int t = threadIdx.x;
    const int row = blockIdx.x;
    const int b = row >> 12;
    build_tw(tw, t);

    const size_t base = (size_t)row * DIM;
    const float* qp = g_q + base;
    const float* rp = g_r + base;
#pragma unroll
    for (int h = 0; h < 4; h++) {
        const int i = t + (h << 8);
        bufA[i] = make_float2(qp[i], rp[i]);
    }
    float2* Z = fft1024(bufA, bufB, tw, t, 0);

    const float2* Fsb = g_Fs + (size_t)b * DIM;
#pragma unroll
    for (int h = 0; h < 4; h++) {
        const int f  = t + (h << 8);
        const int fn = (1024 - f) & 1023;
        const float2 z1 = Z[f];
        const float2 z2 = Z[fn];
        const float2 Fq = make_float2(0.5f * (z1.x + z2.x), 0.5f * (z1.y - z2.y));
        const float dx = z1.x - z2.x, dy = z1.y + z2.y;
        const float2 Fr = make_float2(0.5f * dy, -0.5f * dx);
        const float mag2 = Fr.x * Fr.x + Fr.y * Fr.y;
        const float2 G = make_float2(Fq.x - mag2, -Fq.y);
        bufB[f] = cmulf(G, Fsb[f]);
    }
    float2* res = fft1024(bufB, bufA, tw, t, 1);

    const float* xp = x + base;
    float* op = out + base;
#pragma unroll
    for (int h = 0; h < 4; h++) {
        const int i = t + (h << 8);
        op[i] = xp[i] + res[i].x * (1.0f / 1024.0f);
    }
}

// ============================================================================
// Launch
// ============================================================================
extern "C" void kernel_launch(void* const* d_in, const int* in_sizes, int n_in,
                              void* d_out, int out_size)
{
    const float* x  = (const float*)d_in[0];
    const float* Wq = (const float*)d_in[1];
    const float* bq = (const float*)d_in[2];
    const float* Wk = (const float*)d_in[3];
    const float* bk = (const float*)d_in[4];
    const float* Wv = (const float*)d_in[5];
    const float* bv = (const float*)d_in[6];
    const float* Wr = (const float*)d_in[7];
    const float* br = (const float*)d_in[8];
    float* out = (float*)d_out;

    static bool attr_set = false;
    if (!attr_set) {
        cudaFuncSetAttribute(gemm_mma_kernel,
                             cudaFuncAttributeMaxDynamicSharedMemorySize, SMEM_DYN);
        attr_set = true;
    }

    convert_x_kernel<<<(MROWS * DIM) / 256, 256>>>(x);
    convert_w_kernel<<<dim3((DIM * DIM) / 256, 4), 256>>>(Wq, Wk, Wv, Wr);

    gemm_mma_kernel<<<dim3(DIM / BN, MROWS / BM, 4), 256, SMEM_DYN>>>(bq, bk, bv, br);

    bind_accum_kernel<<<dim3(NCH, BATCH), 256>>>();
    reduce_Fs_kernel<<<dim3(DIM / 256, BATCH), 256>>>();
    output_kernel<<<MROWS, 256>>>(x, out);
}

// round 4
// speedup vs baseline: 3.1417x; 1.1614x over previous
#include <cuda_runtime.h>
#include <cuda_bf16.h>
#include <math.h>
#include <stdint.h>

#define BATCH 4
#define SEQ   4096
#define DIM   1024
#define MROWS (BATCH*SEQ)       // 16384
#define KSTORE 2048             // [hi | lo] per row, bf16
#define NCH   256
#define CROWS (SEQ / NCH)       // 16

// ---- mma.sync GEMM tiling ----
#define BM 128
#define BN 256
#define KITERS 48               // 3072 effective K (3-term split)
#define STAGES 3
#define A_ST (BM * 128)         // 16384 B
#define B_ST (BN * 128)         // 32768 B
#define STAGE_B (A_ST + B_ST)   // 49152
#define SMEM_DYN (STAGES * STAGE_B)   // 147456

// -------- scratch (static device globals; no runtime allocation) -----------
__device__ __nv_bfloat16 g_xe[(size_t)MROWS * KSTORE];   // 64MB  [row][ah|al]
__device__ __nv_bfloat16 g_we[4][(size_t)DIM * KSTORE];  // 16MB
__device__ float  g_q[(size_t)MROWS * DIM];
__device__ float  g_k[(size_t)MROWS * DIM];
__device__ float  g_v[(size_t)MROWS * DIM];
__device__ float  g_r[(size_t)MROWS * DIM];
__device__ float2 g_part[BATCH * NCH * DIM];
__device__ float2 g_Fs[BATCH * DIM];

// ============================================================================
// helpers
// ============================================================================
__device__ __forceinline__ uint32_t smem_u32(const void* p) {
    uint32_t a;
    asm("{ .reg .u64 t; cvta.to.shared.u64 t, %1; cvt.u32.u64 %0, t; }" : "=r"(a) : "l"(p));
    return a;
}

__device__ __forceinline__ void cp16(uint32_t dst, const void* src) {
    asm volatile("cp.async.cg.shared.global [%0], [%1], 16;" :: "r"(dst), "l"(src) : "memory");
}
#define CP_COMMIT() asm volatile("cp.async.commit_group;" ::: "memory")
#define CP_WAIT1()  asm volatile("cp.async.wait_group 1;" ::: "memory")

__device__ __forceinline__ void ldmx4(uint32_t& r0, uint32_t& r1, uint32_t& r2, uint32_t& r3,
                                      uint32_t addr) {
    asm volatile("ldmatrix.sync.aligned.m8n8.x4.shared.b16 {%0,%1,%2,%3}, [%4];"
                 : "=r"(r0), "=r"(r1), "=r"(r2), "=r"(r3) : "r"(addr));
}

__device__ __forceinline__ void mma16816(float* c, uint32_t a0, uint32_t a1, uint32_t a2,
                                         uint32_t a3, uint32_t b0, uint32_t b1) {
    asm volatile(
        "mma.sync.aligned.m16n8k16.row.col.f32.bf16.bf16.f32 "
        "{%0,%1,%2,%3}, {%4,%5,%6,%7}, {%8,%9}, {%0,%1,%2,%3};"
        : "+f"(c[0]), "+f"(c[1]), "+f"(c[2]), "+f"(c[3])
        : "r"(a0), "r"(a1), "r"(a2), "r"(a3), "r"(b0), "r"(b1));
}

__device__ __forceinline__ float tanh_fast(float x) {
    float ax = fabsf(x);
    float e = __expf(-2.0f * ax);
    float t = __fdividef(1.0f - e, 1.0f + e);
    return copysignf(t, x);
}

// swizzled smem byte offset within a (rows x 128B) tile
__device__ __forceinline__ uint32_t swz(uint32_t row, uint32_t cg) {
    return row * 128u + ((cg ^ (row & 7u)) << 4);
}

// ============================================================================
// Conversion: fp32 -> hi/lo bf16 halves  (row-major, [hi(1024) | lo(1024)])
// ============================================================================
__global__ void __launch_bounds__(256) convert_x_kernel(const float* __restrict__ x)
{
    const size_t idx = (size_t)blockIdx.x * 256 + threadIdx.x;
    const size_t row = idx >> 10, d = idx & 1023;
    float v = x[idx];
    __nv_bfloat16 hi = __float2bfloat16(v);
    __nv_bfloat16 lo = __float2bfloat16(v - __bfloat162float(hi));
    g_xe[row * KSTORE + d]        = hi;
    g_xe[row * KSTORE + 1024 + d] = lo;
}

__global__ void __launch_bounds__(256) convert_w_kernel(
    const float* __restrict__ Wq, const float* __restrict__ Wk,
    const float* __restrict__ Wv, const float* __restrict__ Wr)
{
    const int w = blockIdx.y;
    const float* W = (w == 0) ? Wq : (w == 1) ? Wk : (w == 2) ? Wv : Wr;
    const size_t idx = (size_t)blockIdx.x * 256 + threadIdx.x;
    const size_t row = idx >> 10, d = idx & 1023;
    float v = W[idx];
    __nv_bfloat16 hi = __float2bfloat16(v);
    __nv_bfloat16 lo = __float2bfloat16(v - __bfloat162float(hi));
    g_we[w][row * KSTORE + d]        = hi;
    g_we[w][row * KSTORE + 1024 + d] = lo;
}

// ============================================================================
// bf16 mma.sync GEMM, 3-term split, BM=128 x BN=256, 8 warps (warp 64x64)
// ============================================================================
__global__ void __launch_bounds__(256, 1) gemm_mma_kernel(
    const float* __restrict__ bq, const float* __restrict__ bk,
    const float* __restrict__ bv, const float* __restrict__ br)
{
    extern __shared__ char dsm[];
    const uint32_t smem = smem_u32(dsm);

    const int tid = threadIdx.x, wid = tid >> 5, lane = tid & 31;
    const int nb = blockIdx.x, mb = blockIdx.y, sel = blockIdx.z;
    const int wm = wid & 1, wn = wid >> 1;       // warp tile 64(m) x 64(n)
    const float* bias = (sel == 0) ? bq : (sel == 1) ? bk : (sel == 2) ? bv : br;
    float* C = (sel == 0) ? g_q : (sel == 1) ? g_k : (sel == 2) ? g_v : g_r;

    const char* a_base = (const char*)g_xe + (size_t)mb * BM * 4096;
    const char* b_base = (const char*)g_we[sel] + (size_t)nb * BN * 4096;

    const uint32_t crow0 = (uint32_t)(tid >> 3);
    const uint32_t ccg = (uint32_t)(tid & 7);

    float acc[4][8][4];
#pragma unroll
    for (int i = 0; i < 4; i++)
#pragma unroll
        for (int j = 0; j < 8; j++)
#pragma unroll
            for (int q = 0; q < 4; q++) acc[i][j][q] = 0.f;

    auto issue = [&](int stage, int kc) {
        const int akc = (kc < 32) ? kc : kc - 32;
        const int bkc = (kc < 16) ? kc : kc - 16;
        const uint32_t sA = smem + stage * STAGE_B;
        const uint32_t sB = sA + A_ST;
#pragma unroll
        for (int j = 0; j < 4; j++) {
            const uint32_t r = crow0 + 32u * j;
            cp16(sA + swz(r, ccg), a_base + (size_t)r * 4096 + akc * 128 + ccg * 16);
        }
#pragma unroll
        for (int j = 0; j < 8; j++) {
            const uint32_t r = crow0 + 32u * j;
            cp16(sB + swz(r, ccg), b_base + (size_t)r * 4096 + bkc * 128 + ccg * 16);
        }
    };

    issue(0, 0); CP_COMMIT();
    issue(1, 1); CP_COMMIT();

    const uint32_t a_row = (uint32_t)(wm * 64 + (lane & 15));
    const uint32_t a_kg  = (uint32_t)(lane >> 4);
    const uint32_t b_row = (uint32_t)(wn * 64 + (lane & 7) + ((lane >> 4) << 3));
    const uint32_t b_kg  = (uint32_t)((lane >> 3) & 1);

    for (int kc = 0; kc < KITERS; kc++) {
        const int s = kc % STAGES;
        CP_WAIT1();
        __syncthreads();
        const uint32_t sA = smem + s * STAGE_B;
        const uint32_t sB = sA + A_ST;
#pragma unroll
        for (int ks = 0; ks < 4; ks++) {
            uint32_t a[4][4];
#pragma unroll
            for (int mf = 0; mf < 4; mf++)
                ldmx4(a[mf][0], a[mf][1], a[mf][2], a[mf][3],
                      sA + swz(a_row + mf * 16, a_kg + ks * 2));
            uint32_t b[4][4];
#pragma unroll
            for (int nf2 = 0; nf2 < 4; nf2++)
                ldmx4(b[nf2][0], b[nf2][1], b[nf2][2], b[nf2][3],
                      sB + swz(b_row + nf2 * 16, b_kg + ks * 2));
#pragma unroll
            for (int mf = 0; mf < 4; mf++) {
#pragma unroll
                for (int nf2 = 0; nf2 < 4; nf2++) {
                    mma16816(acc[mf][nf2 * 2 + 0], a[mf][0], a[mf][1], a[mf][2], a[mf][3],
                             b[nf2][0], b[nf2][1]);
                    mma16816(acc[mf][nf2 * 2 + 1], a[mf][0], a[mf][1], a[mf][2], a[mf][3],
                             b[nf2][2], b[nf2][3]);
                }
            }
        }
        if (kc + 2 < KITERS) issue((kc + 2) % STAGES, kc + 2);
        CP_COMMIT();
    }

    // epilogue: bias + tanh + fp32 store
#pragma unroll
    for (int mf = 0; mf < 4; mf++) {
        const int r0 = mb * BM + wm * 64 + mf * 16 + (lane >> 2);
        const int r1 = r0 + 8;
#pragma unroll
        for (int nf = 0; nf < 8; nf++) {
            const int col = nb * BN + wn * 64 + nf * 8 + (lane & 3) * 2;
            const float2 b2 = *(const float2*)(bias + col);
            float2 o0, o1;
            o0.x = tanh_fast(acc[mf][nf][0] + b2.x);
            o0.y = tanh_fast(acc[mf][nf][1] + b2.y);
            o1.x = tanh_fast(acc[mf][nf][2] + b2.x);
            o1.y = tanh_fast(acc[mf][nf][3] + b2.y);
            *(float2*)(C + (size_t)r0 * DIM + col) = o0;
            *(float2*)(C + (size_t)r1 * DIM + col) = o1;
        }
    }
}

// ============================================================================
// Radix-4 Stockham FFT, N=1024, 256 threads, 5 stages.
// tw[e] = exp(-2*pi*i*e/1024), e in [0,256). Result in returned pointer
// (= original 'b' after 5 swaps). inv=1: conjugate twiddles (no 1/N scale).
// ============================================================================
__device__ __forceinline__ float2 cmulf(float2 a, float2 b) {
    return make_float2(fmaf(a.x, b.x, -a.y * b.y), fmaf(a.x, b.y, a.y * b.x));
}
__device__ __forceinline__ float2 caddf(float2 a, float2 b) {
    return make_float2(a.x + b.x, a.y + b.y);
}
__device__ __forceinline__ float2 csubf(float2 a, float2 b) {
    return make_float2(a.x - b.x, a.y - b.y);
}

__device__ float2* fft1024_r4(float2* a, float2* b, const float2* tw, int t, int inv)
{
    int m = 1;
#pragma unroll
    for (int s = 0; s < 5; s++) {
        __syncthreads();
        const int k  = t & (m - 1);
        const int jm = t - k;                 // j*m in [0,256)
        const float2 x0 = a[t];
        const float2 x1 = a[t + 256];
        const float2 x2 = a[t + 512];
        const float2 x3 = a[t + 768];
        const float2 t0 = caddf(x0, x2);
        const float2 t1 = caddf(x1, x3);
        const float2 t2 = csubf(x0, x2);
        const float2 d  = csubf(x1, x3);
        // forward: t3 = -i*d ; inverse: t3 = +i*d
        const float2 t3 = inv ? make_float2(-d.y, d.x) : make_float2(d.y, -d.x);
        float2 w1 = tw[jm];
        if (inv) w1.y = -w1.y;
        const float2 w2 = cmulf(w1, w1);
        const float2 w3 = cmulf(w2, w1);
        const int o = 4 * jm + k;
        b[o]         = caddf(t0, t1);
        b[o + m]     = cmulf(w1, caddf(t2, t3));
        b[o + 2 * m] = cmulf(w2, csubf(t0, t1));
        b[o + 3 * m] = cmulf(w3, csubf(t2, t3));
        float2* tmp = a; a = b; b = tmp;
        m <<= 2;
    }
    __syncthreads();
    return a;   // after odd # of swaps: result lives in the original 'b' buffer
}

__device__ __forceinline__ void build_tw256(float2* tw, int t)
{
    // one entry per thread
    float sn, cs;
    sincosf(-2.0f * (float)M_PI * (float)t * (1.0f / 1024.0f), &sn, &cs);
    tw[t] = make_float2(cs, sn);
}

// ============================================================================
// bind + accumulate: Z = FFT(k + i*v); acc += Fk*Fv (Hermitian extraction)
// ============================================================================
__global__ void __launch_bounds__(256) bind_accum_kernel()
{
    __shared__ float2 tw[256];
    __shared__ float2 bufA[1024];
    __shared__ float2 bufB[1024];

    const int t = threadIdx.x;
    const int c = blockIdx.x;
    const int b = blockIdx.y;
    build_tw256(tw, t);

    float2 acc[4];
#pragma unroll
    for (int h = 0; h < 4; h++) acc[h] = make_float2(0.f, 0.f);

    const size_t base = ((size_t)b * SEQ + (size_t)c * CROWS) * DIM;
    for (int r = 0; r < CROWS; r++) {
        const float* kp = g_k + base + (size_t)r * DIM;
        const float* vp = g_v + base + (size_t)r * DIM;
#pragma unroll
        for (int h = 0; h < 4; h++) {
            const int i = t + (h << 8);
            bufA[i] = make_float2(kp[i], vp[i]);
        }
        float2* Z = fft1024_r4(bufA, bufB, tw, t, 0);   // result in bufB region
#pragma unroll
        for (int h = 0; h < 4; h++) {
            const int f  = t + (h << 8);
            const int fn = (1024 - f) & 1023;
            const float2 z1 = Z[f];
            const float2 z2 = Z[fn];
            const float2 Fk = make_float2(0.5f * (z1.x + z2.x), 0.5f * (z1.y - z2.y));
            const float dx = z1.x - z2.x, dy = z1.y + z2.y;
            const float2 Fv = make_float2(0.5f * dy, -0.5f * dx);
            const float2 p = cmulf(Fk, Fv);
            acc[h].x += p.x; acc[h].y += p.y;
        }
        __syncthreads();  // Z reads done before next iteration's FFT overwrites
    }

    float2* outp = g_part + ((size_t)b * NCH + c) * DIM;
#pragma unroll
    for (int h = 0; h < 4; h++) outp[t + (h << 8)] = acc[h];
}

__global__ void reduce_Fs_kernel()
{
    const int f = blockIdx.x * 256 + threadIdx.x;
    const int b = blockIdx.y;
    float2 s = make_float2(0.f, 0.f);
    const float2* p = g_part + (size_t)b * NCH * DIM + f;
    for (int c = 0; c < NCH; c++) {
        const float2 v = p[(size_t)c * DIM];
        s.x += v.x; s.y += v.y;
    }
    g_Fs[b * DIM + f] = s;
}

// ============================================================================
// output: Z = FFT(q + i*r); G = conj(Fq) - |Fr|^2; out = x + ifft(G*Fs).real
// ============================================================================
__global__ void __launch_bounds__(256) output_kernel(
    const float* __restrict__ x, float* __restrict__ out)
{
    __shared__ float2 tw[256];
    __shared__ float2 bufA[1024];
    __shared__ float2 bufB[1024];

    const int t = threadIdx.x;
    const int row = blockIdx.x;
    const int b = row >> 12;
    build_tw256(tw, t);

    const size_t base = (size_t)row * DIM;
    const float* qp = g_q + base;
    const float* rp = g_r + base;
#pragma unroll
    for (int h = 0; h < 4; h++) {
        const int i = t + (h << 8);
        bufA[i] = make_float2(qp[i], rp[i]);
    }
    float2* Z = fft1024_r4(bufA, bufB, tw, t, 0);   // Z in bufB region
    float2* other = (Z == bufA) ? bufB : bufA;      // free buffer (= bufA)

    const float2* Fsb = g_Fs + (size_t)b * DIM;
#pragma unroll
    for (int h = 0; h < 4; h++) {
        const int f  = t + (h << 8);
        const int fn = (1024 - f) & 1023;
        const float2 z1 = Z[f];
        const float2 z2 = Z[fn];
        const float2 Fq = make_float2(0.5f * (z1.x + z2.x), 0.5f * (z1.y - z2.y));
        const float dx = z1.x - z2.x, dy = z1.y + z2.y;
        const float2 Fr = make_float2(0.5f * dy, -0.5f * dx);
        const float mag2 = Fr.x * Fr.x + Fr.y * Fr.y;
        const float2 G = make_float2(Fq.x - mag2, -Fq.y);
        other[f] = cmulf(G, Fsb[f]);                // H into free buffer
    }
    float2* res = fft1024_r4(other, Z, tw, t, 1);   // first sync orders H writes

    const float* xp = x + base;
    float* op = out + base;
#pragma unroll
    for (int h = 0; h < 4; h++) {
        const int i = t + (h << 8);
        op[i] = xp[i] + res[i].x * (1.0f / 1024.0f);
    }
}

// ============================================================================
// Launch
// ============================================================================
extern "C" void kernel_launch(void* const* d_in, const int* in_sizes, int n_in,
                              void* d_out, int out_size)
{
    const float* x  = (const float*)d_in[0];
    const float* Wq = (const float*)d_in[1];
    const float* bq = (const float*)d_in[2];
    const float* Wk = (const float*)d_in[3];
    const float* bk = (const float*)d_in[4];
    const float* Wv = (const float*)d_in[5];
    const float* bv = (const float*)d_in[6];
    const float* Wr = (const float*)d_in[7];
    const float* br = (const float*)d_in[8];
    float* out = (float*)d_out;

    static bool attr_set = false;
    if (!attr_set) {
        cudaFuncSetAttribute(gemm_mma_kernel,
                             cudaFuncAttributeMaxDynamicSharedMemorySize, SMEM_DYN);
        attr_set = true;
    }

    convert_x_kernel<<<(MROWS * DIM) / 256, 256>>>(x);
    convert_w_kernel<<<dim3((DIM * DIM) / 256, 4), 256>>>(Wq, Wk, Wv, Wr);

    gemm_mma_kernel<<<dim3(DIM / BN, MROWS / BM, 4), 256, SMEM_DYN>>>(bq, bk, bv, br);

    bind_accum_kernel<<<dim3(NCH, BATCH), 256>>>();
    reduce_Fs_kernel<<<dim3(DIM / 256, BATCH), 256>>>();
    output_kernel<<<MROWS, 256>>>(x, out);
}